// round 10
// baseline (speedup 1.0000x reference)
#include <cuda_runtime.h>
#include <cuda_bf16.h>
#include <cstdint>

#define BB 2
#define GG 2048
#define HH 4
#define EE 128

#define TQ 32      // q rows per block (8 warps x 4 q-rows)
#define TP 64      // p columns per tile
#define PSPLIT 4   // p-range splits
#define PRANGE (GG / PSPLIT)      // 512
#define NTILE (PRANGE / TP)       // 8
#define NT 256     // threads per attn block (8 warps)

// ---------------- device scratch ----------------
__device__ float g_Q[BB * GG * 128];      // [b][g][h*32+k]
__device__ float g_K[BB * GG * 128];      // [b][g][h*32+k]
__device__ float g_Vt[BB * 128 * GG];     // transposed: [b][h*32+v][g]
__device__ float g_pacc[PSPLIT][BB * GG * 128];  // unnormalized AV partials
__device__ float g_pm[PSPLIT][BB * GG * 4];      // running max per (row,h)
__device__ float g_pl[PSPLIT][BB * GG * 4];      // softmax denom partial

// ---------------- f32x2 helpers ----------------
__device__ __forceinline__ unsigned long long pack2(float a, float b) {
    unsigned long long r;
    asm("mov.b64 %0, {%1, %2};" : "=l"(r) : "f"(a), "f"(b));
    return r;
}
__device__ __forceinline__ void unpack2(unsigned long long v, float& a, float& b) {
    asm("mov.b64 {%0, %1}, %2;" : "=f"(a), "=f"(b) : "l"(v));
}
__device__ __forceinline__ void fma2(unsigned long long& d,
                                     unsigned long long a, unsigned long long b) {
    asm("fma.rn.f32x2 %0, %1, %2, %0;" : "+l"(d) : "l"(a), "l"(b));
}
__device__ __forceinline__ void mul2(unsigned long long& d, unsigned long long a) {
    asm("mul.rn.f32x2 %0, %0, %1;" : "+l"(d) : "l"(a));
}

#define CP_ASYNC16(dst, src) \
    asm volatile("cp.async.cg.shared.global [%0], [%1], 16;" :: "r"(dst), "l"(src))
#define CP_COMMIT() asm volatile("cp.async.commit_group;" ::: "memory")
#define CP_WAIT0()  asm volatile("cp.async.wait_group 0;" ::: "memory")

// =============================================================================
// K0: fused QKV projection; V written globally transposed (d-major).
// 128 threads = 4 warps; warp owns 4 rows; lane owns 4 output cols (float4 W).
// grid = 256 blocks x 16 rows.
// =============================================================================
__global__ __launch_bounds__(128)
void qkv_kernel(const float* __restrict__ hin,
                const float* __restrict__ Wq,
                const float* __restrict__ Wk,
                const float* __restrict__ Wv)
{
    __shared__ float hs[16 * 128];
    const int tid  = threadIdx.x;
    const int row0 = blockIdx.x * 16;

#pragma unroll
    for (int j = 0; j < 4; j++)
        ((float4*)hs)[tid + j * 128] =
            __ldg((const float4*)(hin + (size_t)row0 * 128) + tid + j * 128);
    __syncthreads();

    const int warp = tid >> 5;
    const int lane = tid & 31;
    const int r0   = warp * 4;          // 4 rows per warp
    const int c0   = lane * 4;          // 4 cols per lane
    const int hh   = c0 >> 5;
    const int k    = c0 & 31;

    const float4* wq4 = (const float4*)(Wq + hh * 4096 + k);
    const float4* wk4 = (const float4*)(Wk + hh * 4096 + k);
    const float4* wv4 = (const float4*)(Wv + hh * 4096 + k);

    float4 aq[4], ak[4], av[4];
#pragma unroll
    for (int r = 0; r < 4; r++) {
        aq[r] = make_float4(0.f, 0.f, 0.f, 0.f);
        ak[r] = aq[r]; av[r] = aq[r];
    }

    for (int d = 0; d < 128; d++) {
        const float4 wq = __ldg(wq4 + d * 8);
        const float4 wk = __ldg(wk4 + d * 8);
        const float4 wv = __ldg(wv4 + d * 8);
#pragma unroll
        for (int r = 0; r < 4; r++) {
            const float hv = hs[(r0 + r) * 128 + d];
            aq[r].x += hv * wq.x; aq[r].y += hv * wq.y;
            aq[r].z += hv * wq.z; aq[r].w += hv * wq.w;
            ak[r].x += hv * wk.x; ak[r].y += hv * wk.y;
            ak[r].z += hv * wk.z; ak[r].w += hv * wk.w;
            av[r].x += hv * wv.x; av[r].y += hv * wv.y;
            av[r].z += hv * wv.z; av[r].w += hv * wv.w;
        }
    }

    const int growbase = row0 + r0;
    const int b = growbase >> 11;       // 16 | 2048 -> no batch straddle
#pragma unroll
    for (int r = 0; r < 4; r++) {
        const int grow = growbase + r;
        const int g    = grow & 2047;
        *(float4*)(g_Q + (size_t)grow * 128 + c0) = aq[r];
        *(float4*)(g_K + (size_t)grow * 128 + c0) = ak[r];
        g_Vt[((size_t)(b * 128 + c0 + 0)) * 2048 + g] = av[r].x;
        g_Vt[((size_t)(b * 128 + c0 + 1)) * 2048 + g] = av[r].y;
        g_Vt[((size_t)(b * 128 + c0 + 2)) * 2048 + g] = av[r].z;
        g_Vt[((size_t)(b * 128 + c0 + 3)) * 2048 + g] = av[r].w;
    }
}

// =============================================================================
// K1: fused scores + MLP + online softmax + A@V partials (+ osa pass-through)
// grid = (64 qtiles, 2 batch, 4 psplit) = 512 blocks, 256 thr = 8 warps.
// Warp owns 4 q rows; lane owns p-pair (2*lane, 2*lane+1) of the 64-wide tile.
// Single-buffered cp.async staging; exp-weight buffer overlays the K tile.
// smem = 86,368 B -> 2 blocks/SM.
// =============================================================================
#define SM_QS 0                 /* 32 x 132 = 4224 floats */
#define SM_K  4224              /* 64 x 132 = 8448 floats */
#define SM_V  12672             /* 128 x 68 = 8704 floats */
#define SM_WT 21376             /* 108 ull  = 216 floats  */
#define SMEM_FLOATS 21592
#define SMEM_BYTES (SMEM_FLOATS * 4)

__device__ __forceinline__ void mlp8(const unsigned long long* __restrict__ wtU,
                                     const float* s0v, const float* s1v,
                                     const unsigned long long* o2,
                                     float* y0, float* y1)
{
    unsigned long long x2[8];
#pragma unroll
    for (int h = 0; h < 4; h++) {
        x2[h]     = pack2(s0v[h], s1v[h]);
        x2[4 + h] = o2[h];
    }
    unsigned long long hid[8];
#pragma unroll
    for (int j = 0; j < 8; j++) {
        unsigned long long z = wtU[64 + j];
#pragma unroll
        for (int i = 0; i < 8; i++) fma2(z, wtU[j * 8 + i], x2[i]);
        float zl, zh; unpack2(z, zl, zh);
        hid[j] = pack2(fmaxf(zl, 0.f), fmaxf(zh, 0.f));
    }
#pragma unroll
    for (int h = 0; h < 4; h++) {
        unsigned long long z = wtU[104 + h];
#pragma unroll
        for (int j = 0; j < 8; j++) fma2(z, wtU[72 + h * 8 + j], hid[j]);
        unpack2(z, y0[h], y1[h]);
    }
}

__global__ __launch_bounds__(NT, 2)
void attn_kernel(const float* __restrict__ osa,
                 const float* __restrict__ w1,
                 const float* __restrict__ b1,
                 const float* __restrict__ w2,
                 const float* __restrict__ b2,
                 float* __restrict__ osaCopy,
                 int doCopy)
{
    extern __shared__ float sm[];
    const uint32_t smaddr = (uint32_t)__cvta_generic_to_shared(sm);

    float* Qs = sm + SM_QS;
    unsigned long long* wtU = (unsigned long long*)(sm + SM_WT);

    const int tid  = threadIdx.x;
    const int warp = tid >> 5;
    const int lane = tid & 31;
    const int b    = blockIdx.y;
    const int ps   = blockIdx.z;
    const int q0   = blockIdx.x * TQ;
    const int qw   = warp * 4;
    const int p00  = ps * PRANGE;

    // exp-weight staging overlays the K tile (per-warp 4 KB slice)
    unsigned long long* wsU = (unsigned long long*)(sm + SM_K) + warp * 512;

    if (tid < 108) {
        float v;
        if (tid < 64)       v = __ldg(w1 + tid);
        else if (tid < 72)  v = __ldg(b1 + tid - 64);
        else if (tid < 104) v = __ldg(w2 + tid - 72);
        else                v = __ldg(b2 + tid - 104);
        wtU[tid] = pack2(v, v);
    }

    // Q tile: 32 rows x 128 floats, stride 132 (1024 float4 chunks / 256 thr)
#pragma unroll
    for (int j = 0; j < 4; j++) {
        const int c  = tid + j * 256;
        const int r  = c >> 5;
        const int cg = c & 31;
        ((float4*)(Qs + r * 132))[cg] =
            __ldg((const float4*)(g_Q + (size_t)(b * GG + q0 + r) * 128) + cg);
    }

    unsigned long long acc[4][4];       // packed over p-parity
    float m[4][4], lln[4][4];           // warp-uniform max, per-lane l
#pragma unroll
    for (int q = 0; q < 4; q++)
#pragma unroll
        for (int h = 0; h < 4; h++) { acc[q][h] = 0ULL; m[q][h] = -1e30f; lln[q][h] = 0.f; }

    for (int pt = 0; pt < NTILE; pt++) {
        const int pg0 = p00 + pt * TP;

        // ---- prefetch osa for q-pair 0 ----
        unsigned long long o2a[2][4];
#pragma unroll
        for (int s = 0; s < 2; s++) {
            const int qg = q0 + qw + s;
#pragma unroll
            for (int h = 0; h < 4; h++) {
                const size_t idx = ((size_t)(h * BB + b) * GG + qg) * GG + pg0 + 2 * lane;
                o2a[s][h] = __ldcs((const unsigned long long*)(osa + idx));
            }
        }

        __syncthreads();   // prev tile fully consumed

        // ---- stage K (row-permuted) and Vt ----
#pragma unroll
        for (int j = 0; j < 8; j++) {
            const int c  = tid + j * 256;         // 0..2047
            const int kr = c >> 5;
            const int kc = (c & 31) * 4;
            const int pr = (kr >> 1) + ((kr & 1) << 5);
            CP_ASYNC16(smaddr + (uint32_t)(SM_K + pr * 132 + kc) * 4u,
                       g_K + ((size_t)(b * GG + pg0 + kr)) * 128 + kc);
            const int vd = c >> 4;
            const int vo = (c & 15) * 4;
            CP_ASYNC16(smaddr + (uint32_t)(SM_V + vd * 68 + vo) * 4u,
                       g_Vt + ((size_t)(b * 128 + vd)) * 2048 + pg0 + vo);
        }
        CP_COMMIT();
        CP_WAIT0();
        __syncthreads();

        const float* Ks = sm + SM_K;
        const float* Vt = sm + SM_V;

        // ---- osa copy pair 0 (data long arrived) ----
        if (doCopy) {
#pragma unroll
            for (int s = 0; s < 2; s++) {
                const int qg = q0 + qw + s;
#pragma unroll
                for (int h = 0; h < 4; h++) {
                    const size_t idx = ((size_t)(h * BB + b) * GG + qg) * GG + pg0 + 2 * lane;
                    __stcs((unsigned long long*)(osaCopy + idx), o2a[s][h]);
                }
            }
        }

        // ---- scores for all 4 q rows (K gathers amortized 4x) ----
        float s0[4][4], s1[4][4];
        {
            const ulonglong2* kR0 = (const ulonglong2*)(Ks + lane * 132);
            const ulonglong2* kR1 = (const ulonglong2*)(Ks + (lane + 32) * 132);
#pragma unroll
            for (int h = 0; h < 4; h++) {
                unsigned long long a0[4], a1[4];
#pragma unroll
                for (int q = 0; q < 4; q++) { a0[q] = 0ULL; a1[q] = 0ULL; }
#pragma unroll
                for (int u = 0; u < 8; u++) {
                    const ulonglong2 k0 = kR0[h * 8 + u];
                    const ulonglong2 k1 = kR1[h * 8 + u];
#pragma unroll
                    for (int q = 0; q < 4; q++) {
                        const ulonglong2 qa =
                            ((const ulonglong2*)(Qs + (qw + q) * 132))[h * 8 + u];
                        fma2(a0[q], qa.x, k0.x); fma2(a0[q], qa.y, k0.y);
                        fma2(a1[q], qa.x, k1.x); fma2(a1[q], qa.y, k1.y);
                    }
                }
#pragma unroll
                for (int q = 0; q < 4; q++) {
                    float x, y;
                    unpack2(a0[q], x, y); s0[q][h] = x + y;
                    unpack2(a1[q], x, y); s1[q][h] = x + y;
                }
            }
        }

        // ---- load osa for q-pair 1 (latency hidden by pair-0 MLP/softmax) ----
        unsigned long long o2b[2][4];
#pragma unroll
        for (int s = 0; s < 2; s++) {
            const int qg = q0 + qw + 2 + s;
#pragma unroll
            for (int h = 0; h < 4; h++) {
                const size_t idx = ((size_t)(h * BB + b) * GG + qg) * GG + pg0 + 2 * lane;
                o2b[s][h] = __ldcs((const unsigned long long*)(osa + idx));
            }
        }

        __syncthreads();   // all warps done reading K -> ws overlay safe

        // ---- MLP + softmax, two q-pair passes ----
#pragma unroll
        for (int pair = 0; pair < 2; pair++) {
            float y0[2][4], y1[2][4];
#pragma unroll
            for (int s = 0; s < 2; s++) {
                const int qi = pair * 2 + s;
                mlp8(wtU, s0[qi], s1[qi],
                     pair == 0 ? o2a[s] : o2b[s], y0[s], y1[s]);
            }
            if (pair == 1 && doCopy) {
#pragma unroll
                for (int s = 0; s < 2; s++) {
                    const int qg = q0 + qw + 2 + s;
#pragma unroll
                    for (int h = 0; h < 4; h++) {
                        const size_t idx =
                            ((size_t)(h * BB + b) * GG + qg) * GG + pg0 + 2 * lane;
                        __stcs((unsigned long long*)(osaCopy + idx), o2b[s][h]);
                    }
                }
            }

            bool need = false;
#pragma unroll
            for (int s = 0; s < 2; s++)
#pragma unroll
                for (int h = 0; h < 4; h++)
                    need |= (fmaxf(y0[s][h], y1[s][h]) > m[pair * 2 + s][h]);

            if (__ballot_sync(0xffffffffu, need)) {
#pragma unroll
                for (int s = 0; s < 2; s++) {
                    const int qi = pair * 2 + s;
#pragma unroll
                    for (int h = 0; h < 4; h++) {
                        float t = fmaxf(y0[s][h], y1[s][h]);
#pragma unroll
                        for (int off = 16; off; off >>= 1)
                            t = fmaxf(t, __shfl_xor_sync(0xffffffffu, t, off));
                        if (t > m[qi][h]) {          // warp-uniform
                            const float corr = __expf(m[qi][h] - t);
                            lln[qi][h] *= corr;
                            mul2(acc[qi][h], pack2(corr, corr));
                            m[qi][h] = t;
                        }
                    }
                }
            }
#pragma unroll
            for (int s = 0; s < 2; s++) {
                const int qi = pair * 2 + s;
#pragma unroll
                for (int h = 0; h < 4; h++) {
                    const float wa = __expf(y0[s][h] - m[qi][h]);
                    const float wb = __expf(y1[s][h] - m[qi][h]);
                    lln[qi][h] += wa + wb;
                    wsU[(qi * 4 + h) * 32 + lane] = pack2(wa, wb);
                }
            }
        }
        __syncwarp();

        // ---- AV: lane = v; V gathers amortized over 4 q rows ----
#pragma unroll
        for (int h = 0; h < 4; h++) {
            const ulonglong2* vR = (const ulonglong2*)(Vt + (h * 32 + lane) * 68);
            const ulonglong2* w0 = (const ulonglong2*)(wsU + (0 * 4 + h) * 32);
            const ulonglong2* w1p = (const ulonglong2*)(wsU + (1 * 4 + h) * 32);
            const ulonglong2* w2p = (const ulonglong2*)(wsU + (2 * 4 + h) * 32);
            const ulonglong2* w3p = (const ulonglong2*)(wsU + (3 * 4 + h) * 32);
            unsigned long long A0 = acc[0][h], A1 = acc[1][h];
            unsigned long long A2 = acc[2][h], A3 = acc[3][h];
#pragma unroll
            for (int jg = 0; jg < 16; jg++) {
                const ulonglong2 v2 = vR[jg];
                const ulonglong2 wa = w0[jg];
                const ulonglong2 wb = w1p[jg];
                const ulonglong2 wc = w2p[jg];
                const ulonglong2 wd = w3p[jg];
                fma2(A0, wa.x, v2.x); fma2(A0, wa.y, v2.y);
                fma2(A1, wb.x, v2.x); fma2(A1, wb.y, v2.y);
                fma2(A2, wc.x, v2.x); fma2(A2, wc.y, v2.y);
                fma2(A3, wd.x, v2.x); fma2(A3, wd.y, v2.y);
            }
            acc[0][h] = A0; acc[1][h] = A1; acc[2][h] = A2; acc[3][h] = A3;
        }
    }

    // ---- epilogue: unnormalized partials + (m, l) ----
#pragma unroll
    for (int q = 0; q < 4; q++) {
        const int qg  = q0 + qw + q;
        const int row = b * GG + qg;
#pragma unroll
        for (int h = 0; h < 4; h++) {
            float ls = lln[q][h];
#pragma unroll
            for (int off = 16; off; off >>= 1)
                ls += __shfl_xor_sync(0xffffffffu, ls, off);
            if (lane == 0) {
                g_pm[ps][row * 4 + h] = m[q][h];
                g_pl[ps][row * 4 + h] = ls;
            }
            float x, y; unpack2(acc[q][h], x, y);
            g_pacc[ps][(size_t)row * 128 + h * 32 + lane] = x + y;
        }
    }
}

// =============================================================================
// K2: combine 4 p-split partials + output projection.
// =============================================================================
__global__ __launch_bounds__(128)
void outproj_kernel(const float* __restrict__ Wout,
                    float* __restrict__ out)
{
    __shared__ float hs[8 * 128];
    __shared__ float fc[8][4][PSPLIT];
    const int tid  = threadIdx.x;
    const int row0 = blockIdx.x * 8;

    if (tid < 32) {
        const int r = tid >> 2, h = tid & 3;
        const int idx = (row0 + r) * 4 + h;
        float mm[PSPLIT], ll[PSPLIT];
        float M = -1e30f;
#pragma unroll
        for (int p = 0; p < PSPLIT; p++) {
            mm[p] = g_pm[p][idx];
            ll[p] = g_pl[p][idx];
            M = fmaxf(M, mm[p]);
        }
        float L = 0.f, e[PSPLIT];
#pragma unroll
        for (int p = 0; p < PSPLIT; p++) {
            e[p] = __expf(mm[p] - M);
            L += ll[p] * e[p];
        }
#pragma unroll
        for (int p = 0; p < PSPLIT; p++) fc[r][h][p] = e[p] / L;
    }
    __syncthreads();

    for (int i = tid; i < 8 * 128; i += 128) {
        const int r = i >> 7, c = i & 127, h = c >> 5;
        float v = 0.f;
#pragma unroll
        for (int p = 0; p < PSPLIT; p++)
            v += g_pacc[p][(size_t)(row0 + r) * 128 + c] * fc[r][h][p];
        hs[i] = v;
    }
    __syncthreads();

    float a[8];
#pragma unroll
    for (int r = 0; r < 8; r++) a[r] = 0.f;

    for (int t = 0; t < 128; t += 4) {
        float w[4];
#pragma unroll
        for (int u = 0; u < 4; u++) w[u] = __ldg(Wout + (t + u) * 128 + tid);
#pragma unroll
        for (int u = 0; u < 4; u++)
#pragma unroll
            for (int r = 0; r < 8; r++) a[r] += hs[r * 128 + t + u] * w[u];
    }
#pragma unroll
    for (int r = 0; r < 8; r++)
        out[(size_t)(row0 + r) * 128 + tid] = a[r];
}

// =============================================================================
extern "C" void kernel_launch(void* const* d_in, const int* in_sizes, int n_in,
                              void* d_out, int out_size)
{
    const float* hin  = (const float*)d_in[0];
    const float* osa  = (const float*)d_in[1];
    const float* Wq   = (const float*)d_in[2];
    const float* Wk   = (const float*)d_in[3];
    const float* Wv   = (const float*)d_in[4];
    const float* Wout = (const float*)d_in[5];
    const float* w1   = (const float*)d_in[6];
    const float* b1   = (const float*)d_in[7];
    const float* w2   = (const float*)d_in[8];
    const float* b2   = (const float*)d_in[9];
    (void)in_sizes; (void)n_in;

    float* out = (float*)d_out;

    const int OUT_ELEMS = BB * GG * EE;
    const long long OSA_ELEMS = (long long)HH * BB * GG * GG;
    const int doCopy = ((long long)out_size >= OUT_ELEMS + OSA_ELEMS) ? 1 : 0;
    float* osaCopy = doCopy ? (out + OUT_ELEMS) : out;

    cudaFuncSetAttribute(attn_kernel,
                         cudaFuncAttributeMaxDynamicSharedMemorySize, SMEM_BYTES);

    qkv_kernel<<<BB * GG / 16, 128>>>(hin, Wq, Wk, Wv);
    attn_kernel<<<dim3(GG / TQ, BB, PSPLIT), NT, SMEM_BYTES>>>(
        osa, w1, b1, w2, b2, osaCopy, doCopy);
    outproj_kernel<<<BB * GG / 8, 128>>>(Wout, out);
}